// round 1
// baseline (speedup 1.0000x reference)
#include <cuda_runtime.h>
#include <math.h>

#define D_    1024
#define NH_   16
#define DH_   64
#define DM_   4096
#define B_    2
#define S_    2048
#define M_    (B_*S_)   /* 4096 rows */

// ---------------- scratch (static device allocations; no cudaMalloc) ----------------
__device__ float g_h1  [(size_t)M_*D_];     // LN1 output
__device__ float g_qkv [(size_t)M_*3*D_];   // fused QKV, layout [b,s,(h,e)] x {Q,K,V}
__device__ float g_ctx [(size_t)M_*D_];     // attention context [b,s,(h,e)]
__device__ float g_x1  [(size_t)M_*D_];     // x + attn_out (first residual)
__device__ float g_h2  [(size_t)M_*D_];     // LN2 output
__device__ float g_mid [(size_t)M_*DM_];    // MLP hidden (post-GELU)
__device__ float g_wqkv[(size_t)D_*3*D_];   // repacked [D, 3*NH*DH] weight

// ---------------- helpers ----------------
__device__ __forceinline__ float gelu_exact(float x) {
    return 0.5f * x * (1.0f + erff(x * 0.70710678118654752440f));
}

// ---------------- QKV weight repack: [NH,D,DH] x3 -> [D, 3*NH*DH] ----------------
__global__ __launch_bounds__(256) void pack_qkv_kernel(
    const float* __restrict__ WQ, const float* __restrict__ WK,
    const float* __restrict__ WV, float* __restrict__ Wp)
{
    int idx = blockIdx.x * 256 + threadIdx.x;      // 0 .. D_*3*D_-1
    int col = idx % (3 * D_);
    int d   = idx / (3 * D_);
    int seg = col >> 10;          // 0:Q 1:K 2:V
    int hc  = col & 1023;
    int h   = hc >> 6;
    int e   = hc & 63;
    const float* W = (seg == 0) ? WQ : (seg == 1) ? WK : WV;
    Wp[idx] = W[((size_t)h * D_ + d) * DH_ + e];
}

// ---------------- LayerNorm: one block per row (D=1024, 256 thr x float4) ----------------
__global__ __launch_bounds__(256) void ln_kernel(
    const float* __restrict__ x, const float* __restrict__ w,
    const float* __restrict__ b, float* __restrict__ out)
{
    int row = blockIdx.x;
    int t   = threadIdx.x;
    const float4* xr = (const float4*)(x + (size_t)row * D_);
    float4 v = xr[t];
    float s  = v.x + v.y + v.z + v.w;
    float sq = v.x*v.x + v.y*v.y + v.z*v.z + v.w*v.w;
    #pragma unroll
    for (int o = 16; o; o >>= 1) {
        s  += __shfl_xor_sync(0xFFFFFFFFu, s,  o);
        sq += __shfl_xor_sync(0xFFFFFFFFu, sq, o);
    }
    __shared__ float ss[8], sqs[8];
    int wid = t >> 5, lid = t & 31;
    if (lid == 0) { ss[wid] = s; sqs[wid] = sq; }
    __syncthreads();
    s = 0.f; sq = 0.f;
    #pragma unroll
    for (int i = 0; i < 8; i++) { s += ss[i]; sq += sqs[i]; }
    float mu  = s  * (1.0f / D_);
    float var = sq * (1.0f / D_) - mu * mu;
    float rs  = rsqrtf(var + 1e-5f);
    float4 wv = ((const float4*)w)[t];
    float4 bv = ((const float4*)b)[t];
    float4 o;
    o.x = (v.x - mu) * rs * wv.x + bv.x;
    o.y = (v.y - mu) * rs * wv.y + bv.y;
    o.z = (v.z - mu) * rs * wv.z + bv.z;
    o.w = (v.w - mu) * rs * wv.w + bv.w;
    ((float4*)(out + (size_t)row * D_))[t] = o;
}

// ---------------- SGEMM: C[M,N] = A[M,K] @ B[K,N], 128x128x8 tile, 8x8/thread ----------------
// EPI: 0 = plain, 1 = +resid, 2 = gelu(acc+bias), 3 = acc+bias+resid
template<int EPI>
__global__ __launch_bounds__(256) void sgemm_kernel(
    const float* __restrict__ A, const float* __restrict__ B,
    float* __restrict__ C, int M, int N, int K,
    const float* __restrict__ bias, const float* __restrict__ resid)
{
    __shared__ float As[8][128];
    __shared__ float Bs[8][128];
    int tid  = threadIdx.x;
    int brow = blockIdx.y * 128;
    int bcol = blockIdx.x * 128;
    int arow = tid >> 1;
    int acol = (tid & 1) << 2;
    int brl  = tid >> 5;
    int bcl  = (tid & 31) << 2;
    int ty   = tid >> 4, tx = tid & 15;

    float acc[8][8];
    #pragma unroll
    for (int i = 0; i < 8; i++)
        #pragma unroll
        for (int j = 0; j < 8; j++) acc[i][j] = 0.f;

    const float* Ap = A + (size_t)(brow + arow) * K + acol;
    const float* Bp = B + (size_t)brl * N + bcol + bcl;

    for (int k0 = 0; k0 < K; k0 += 8) {
        float4 av = *(const float4*)(Ap + k0);
        float4 bv = *(const float4*)(Bp + (size_t)k0 * N);
        As[acol + 0][arow] = av.x;
        As[acol + 1][arow] = av.y;
        As[acol + 2][arow] = av.z;
        As[acol + 3][arow] = av.w;
        *(float4*)&Bs[brl][bcl] = bv;
        __syncthreads();
        #pragma unroll
        for (int k = 0; k < 8; k++) {
            float4 a0 = *(const float4*)&As[k][ty * 8];
            float4 a1 = *(const float4*)&As[k][ty * 8 + 4];
            float4 b0 = *(const float4*)&Bs[k][tx * 8];
            float4 b1 = *(const float4*)&Bs[k][tx * 8 + 4];
            float ar[8] = {a0.x, a0.y, a0.z, a0.w, a1.x, a1.y, a1.z, a1.w};
            float br[8] = {b0.x, b0.y, b0.z, b0.w, b1.x, b1.y, b1.z, b1.w};
            #pragma unroll
            for (int i = 0; i < 8; i++)
                #pragma unroll
                for (int j = 0; j < 8; j++)
                    acc[i][j] += ar[i] * br[j];
        }
        __syncthreads();
    }

    int row0 = brow + ty * 8;
    int col0 = bcol + tx * 8;
    #pragma unroll
    for (int i = 0; i < 8; i++) {
        size_t off = (size_t)(row0 + i) * N + col0;
        #pragma unroll
        for (int j4 = 0; j4 < 8; j4 += 4) {
            float4 r;
            r.x = acc[i][j4 + 0]; r.y = acc[i][j4 + 1];
            r.z = acc[i][j4 + 2]; r.w = acc[i][j4 + 3];
            if (EPI == 2 || EPI == 3) {
                float4 bb = *(const float4*)(bias + col0 + j4);
                r.x += bb.x; r.y += bb.y; r.z += bb.z; r.w += bb.w;
            }
            if (EPI == 1 || EPI == 3) {
                float4 rv = *(const float4*)(resid + off + j4);
                r.x += rv.x; r.y += rv.y; r.z += rv.z; r.w += rv.w;
            }
            if (EPI == 2) {
                r.x = gelu_exact(r.x); r.y = gelu_exact(r.y);
                r.z = gelu_exact(r.z); r.w = gelu_exact(r.w);
            }
            *(float4*)(C + off + j4) = r;
        }
    }
}

// ---------------- Causal flash attention (fp32, online softmax) ----------------
// grid (S/128, NH, B); 128 threads; thread t owns query row blockIdx.x*128+t.
__global__ __launch_bounds__(128) void attn_kernel(
    const float* __restrict__ qkv, float* __restrict__ ctx)
{
    const int C3 = 3 * D_;
    int b = blockIdx.z, h = blockIdx.y;
    int q = blockIdx.x * 128 + threadIdx.x;
    const float* base = qkv + (size_t)b * S_ * C3 + h * DH_;

    __shared__ float Ks[16][DH_];
    __shared__ float Vs[16][DH_];

    float qreg[DH_];
    {
        const float4* qp = (const float4*)(base + (size_t)q * C3);
        #pragma unroll
        for (int i = 0; i < 16; i++) {
            float4 v = qp[i];
            qreg[4*i+0] = v.x; qreg[4*i+1] = v.y;
            qreg[4*i+2] = v.z; qreg[4*i+3] = v.w;
        }
    }
    float acc[DH_];
    #pragma unroll
    for (int i = 0; i < DH_; i++) acc[i] = 0.f;
    float m = -1e30f, l = 0.f;

    int qmax = blockIdx.x * 128 + 127;
    for (int kt = 0; kt <= qmax; kt += 16) {
        // cooperative load of K,V tile (16 rows x 64 floats each)
        #pragma unroll
        for (int it = 0; it < 2; it++) {
            int flat = it * 128 + threadIdx.x;   // 0..255
            int r  = flat >> 4;
            int c4 = flat & 15;
            ((float4*)Ks[r])[c4] = ((const float4*)(base +     D_ + (size_t)(kt + r) * C3))[c4];
            ((float4*)Vs[r])[c4] = ((const float4*)(base + 2 * D_ + (size_t)(kt + r) * C3))[c4];
        }
        __syncthreads();

        if (q >= kt) {  // at least key kt is causally valid for this query
            float s[16];
            #pragma unroll
            for (int kk = 0; kk < 16; kk++) {
                const float4* kr = (const float4*)Ks[kk];
                float sa0 = 0.f, sa1 = 0.f, sa2 = 0.f, sa3 = 0.f;
                #pragma unroll
                for (int d4 = 0; d4 < 16; d4 += 4) {
                    float4 k0 = kr[d4 + 0], k1 = kr[d4 + 1], k2 = kr[d4 + 2], k3 = kr[d4 + 3];
                    sa0 += qreg[4*d4+ 0]*k0.x + qreg[4*d4+ 1]*k0.y + qreg[4*d4+ 2]*k0.z + qreg[4*d4+ 3]*k0.w;
                    sa1 += qreg[4*d4+ 4]*k1.x + qreg[4*d4+ 5]*k1.y + qreg[4*d4+ 6]*k1.z + qreg[4*d4+ 7]*k1.w;
                    sa2 += qreg[4*d4+ 8]*k2.x + qreg[4*d4+ 9]*k2.y + qreg[4*d4+10]*k2.z + qreg[4*d4+11]*k2.w;
                    sa3 += qreg[4*d4+12]*k3.x + qreg[4*d4+13]*k3.y + qreg[4*d4+14]*k3.z + qreg[4*d4+15]*k3.w;
                }
                float sc = (sa0 + sa1) + (sa2 + sa3);
                s[kk] = (kt + kk <= q) ? sc * 0.125f : -1e30f;
            }
            float tmax = -1e30f;
            #pragma unroll
            for (int kk = 0; kk < 16; kk++) tmax = fmaxf(tmax, s[kk]);
            float mn = fmaxf(m, tmax);
            float rescale = __expf(m - mn);
            l *= rescale;
            #pragma unroll
            for (int d = 0; d < DH_; d++) acc[d] *= rescale;
            m = mn;
            #pragma unroll
            for (int kk = 0; kk < 16; kk++) {
                float p = __expf(s[kk] - mn);
                l += p;
                const float4* vr = (const float4*)Vs[kk];
                #pragma unroll
                for (int d4 = 0; d4 < 16; d4++) {
                    float4 v = vr[d4];
                    acc[4*d4+0] += p * v.x;
                    acc[4*d4+1] += p * v.y;
                    acc[4*d4+2] += p * v.z;
                    acc[4*d4+3] += p * v.w;
                }
            }
        }
        __syncthreads();
    }

    float inv = 1.0f / l;
    float4* op = (float4*)(ctx + ((size_t)b * S_ + q) * D_ + h * DH_);
    #pragma unroll
    for (int d4 = 0; d4 < 16; d4++) {
        float4 o;
        o.x = acc[4*d4+0] * inv; o.y = acc[4*d4+1] * inv;
        o.z = acc[4*d4+2] * inv; o.w = acc[4*d4+3] * inv;
        op[d4] = o;
    }
}

// ---------------- launch ----------------
extern "C" void kernel_launch(void* const* d_in, const int* in_sizes, int n_in,
                              void* d_out, int out_size)
{
    const float* x    = (const float*)d_in[0];
    const float* WQ   = (const float*)d_in[1];
    const float* WK   = (const float*)d_in[2];
    const float* WV   = (const float*)d_in[3];
    const float* WO   = (const float*)d_in[4];   // [NH,DH,D] flat == [1024,1024] row-major
    const float* W1   = (const float*)d_in[5];   // [1024,4096] row-major
    const float* b1   = (const float*)d_in[6];
    const float* W2   = (const float*)d_in[7];   // [4096,1024] row-major
    const float* b2   = (const float*)d_in[8];
    const float* ln1w = (const float*)d_in[9];
    const float* ln1b = (const float*)d_in[10];
    const float* ln2w = (const float*)d_in[11];
    const float* ln2b = (const float*)d_in[12];
    float* out = (float*)d_out;

    float *h1, *qkv, *ctx, *x1, *h2, *mid, *wqkv;
    cudaGetSymbolAddress((void**)&h1,   g_h1);
    cudaGetSymbolAddress((void**)&qkv,  g_qkv);
    cudaGetSymbolAddress((void**)&ctx,  g_ctx);
    cudaGetSymbolAddress((void**)&x1,   g_x1);
    cudaGetSymbolAddress((void**)&h2,   g_h2);
    cudaGetSymbolAddress((void**)&mid,  g_mid);
    cudaGetSymbolAddress((void**)&wqkv, g_wqkv);

    // 1. repack QKV weights -> [D, 3*NH*DH]
    pack_qkv_kernel<<<(D_ * 3 * D_) / 256, 256>>>(WQ, WK, WV, wqkv);
    // 2. LN1
    ln_kernel<<<M_, 256>>>(x, ln1w, ln1b, h1);
    // 3. QKV projection: [4096,1024] @ [1024,3072]
    {
        dim3 g(3 * D_ / 128, M_ / 128);
        sgemm_kernel<0><<<g, 256>>>(h1, wqkv, qkv, M_, 3 * D_, D_, nullptr, nullptr);
    }
    // 4. causal attention
    {
        dim3 g(S_ / 128, NH_, B_);
        attn_kernel<<<g, 128>>>(qkv, ctx);
    }
    // 5. output projection + residual: x1 = x + ctx @ WO
    {
        dim3 g(D_ / 128, M_ / 128);
        sgemm_kernel<1><<<g, 256>>>(ctx, WO, x1, M_, D_, D_, nullptr, x);
    }
    // 6. LN2
    ln_kernel<<<M_, 256>>>(x1, ln2w, ln2b, h2);
    // 7. MLP up + GELU: mid = gelu(h2 @ W1 + b1)
    {
        dim3 g(DM_ / 128, M_ / 128);
        sgemm_kernel<2><<<g, 256>>>(h2, W1, mid, M_, DM_, D_, b1, nullptr);
    }
    // 8. MLP down + bias + residual: out = x1 + mid @ W2 + b2
    {
        dim3 g(D_ / 128, M_ / 128);
        sgemm_kernel<3><<<g, 256>>>(mid, W2, out, M_, D_, DM_, b2, x1);
    }
}

// round 5
// speedup vs baseline: 1.6553x; 1.6553x over previous
#include <cuda_runtime.h>
#include <math.h>
#include <stdint.h>

#define D_    1024
#define NH_   16
#define DH_   64
#define DM_   4096
#define B_    2
#define S_    2048
#define M_    (B_*S_)   /* 4096 rows */

// ---------------- scratch (static device allocations; no cudaMalloc) ----------------
__device__ float g_h1  [(size_t)M_*D_];     // LN1 output (tf32-rounded)
__device__ float g_qkv [(size_t)M_*3*D_];   // fused QKV, layout [b,s,(h,e)] x {Q,K,V}
__device__ float g_ctx [(size_t)M_*D_];     // attention context (tf32-rounded)
__device__ float g_x1  [(size_t)M_*D_];     // x + attn_out (first residual)
__device__ float g_h2  [(size_t)M_*D_];     // LN2 output (tf32-rounded)
__device__ float g_mid [(size_t)M_*DM_];    // MLP hidden post-GELU (tf32-rounded)
__device__ float g_wqkv[(size_t)D_*3*D_];   // repacked QKV weight (tf32-rounded)
__device__ float g_wo  [(size_t)D_*D_];     // tf32-rounded WO
__device__ float g_w1  [(size_t)D_*DM_];    // tf32-rounded W1
__device__ float g_w2  [(size_t)DM_*D_];    // tf32-rounded W2

// ---------------- helpers ----------------
__device__ __forceinline__ float gelu_exact(float x) {
    return 0.5f * x * (1.0f + erff(x * 0.70710678118654752440f));
}
__device__ __forceinline__ float tf32r(float x) {
    float y;
    asm("cvt.rna.tf32.f32 %0, %1;" : "=f"(y) : "f"(x));
    return y;
}
__device__ __forceinline__ void cpasync16(uint32_t dst, const void* src) {
    asm volatile("cp.async.cg.shared.global [%0], [%1], 16;" :: "r"(dst), "l"(src));
}
__device__ __forceinline__ void cpcommit() {
    asm volatile("cp.async.commit_group;");
}
template<int N>
__device__ __forceinline__ void cpwait() {
    asm volatile("cp.async.wait_group %0;" :: "n"(N));
}
__device__ __forceinline__ void mma_tf32(float c[4], uint32_t a0, uint32_t a1,
                                         uint32_t a2, uint32_t a3,
                                         uint32_t b0, uint32_t b1) {
    asm volatile(
        "mma.sync.aligned.m16n8k8.row.col.f32.tf32.tf32.f32 "
        "{%0,%1,%2,%3}, {%4,%5,%6,%7}, {%8,%9}, {%0,%1,%2,%3};"
        : "+f"(c[0]), "+f"(c[1]), "+f"(c[2]), "+f"(c[3])
        : "r"(a0), "r"(a1), "r"(a2), "r"(a3), "r"(b0), "r"(b1));
}

// ---------------- elementwise tf32 convert ----------------
__global__ __launch_bounds__(256) void cvt_kernel(const float* __restrict__ in,
                                                  float* __restrict__ out, int n) {
    int i = blockIdx.x * 256 + threadIdx.x;
    if (i < n) out[i] = tf32r(in[i]);
}

// ---------------- QKV weight repack: [NH,D,DH] x3 -> [D, 3*NH*DH], tf32-rounded --------
__global__ __launch_bounds__(256) void pack_qkv_kernel(
    const float* __restrict__ WQ, const float* __restrict__ WK,
    const float* __restrict__ WV, float* __restrict__ Wp)
{
    int idx = blockIdx.x * 256 + threadIdx.x;
    int col = idx % (3 * D_);
    int d   = idx / (3 * D_);
    int seg = col >> 10;
    int hc  = col & 1023;
    int h   = hc >> 6;
    int e   = hc & 63;
    const float* W = (seg == 0) ? WQ : (seg == 1) ? WK : WV;
    Wp[idx] = tf32r(W[((size_t)h * D_ + d) * DH_ + e]);
}

// ---------------- LayerNorm (optionally tf32-rounded output) ----------------
template<bool ROUND>
__global__ __launch_bounds__(256) void ln_kernel(
    const float* __restrict__ x, const float* __restrict__ w,
    const float* __restrict__ b, float* __restrict__ out)
{
    int row = blockIdx.x;
    int t   = threadIdx.x;
    const float4* xr = (const float4*)(x + (size_t)row * D_);
    float4 v = xr[t];
    float s  = v.x + v.y + v.z + v.w;
    float sq = v.x*v.x + v.y*v.y + v.z*v.z + v.w*v.w;
    #pragma unroll
    for (int o = 16; o; o >>= 1) {
        s  += __shfl_xor_sync(0xFFFFFFFFu, s,  o);
        sq += __shfl_xor_sync(0xFFFFFFFFu, sq, o);
    }
    __shared__ float ss[8], sqs[8];
    int wid = t >> 5, lid = t & 31;
    if (lid == 0) { ss[wid] = s; sqs[wid] = sq; }
    __syncthreads();
    s = 0.f; sq = 0.f;
    #pragma unroll
    for (int i = 0; i < 8; i++) { s += ss[i]; sq += sqs[i]; }
    float mu  = s  * (1.0f / D_);
    float var = sq * (1.0f / D_) - mu * mu;
    float rs  = rsqrtf(var + 1e-5f);
    float4 wv = ((const float4*)w)[t];
    float4 bv = ((const float4*)b)[t];
    float4 o;
    o.x = (v.x - mu) * rs * wv.x + bv.x;
    o.y = (v.y - mu) * rs * wv.y + bv.y;
    o.z = (v.z - mu) * rs * wv.z + bv.z;
    o.w = (v.w - mu) * rs * wv.w + bv.w;
    if (ROUND) { o.x = tf32r(o.x); o.y = tf32r(o.y); o.z = tf32r(o.z); o.w = tf32r(o.w); }
    ((float4*)(out + (size_t)row * D_))[t] = o;
}

// ---------------- TF32 tensor-core GEMM: C[M,N] = A[M,K] @ B[K,N] ----------------
// 128x128x16 block tile, 8 warps (2x4) of 64x32, m16n8k8 TF32 mma, cp.async 2-stage.
// EPI: 0 = plain, 1 = +resid, 2 = tf32(gelu(acc+bias)), 3 = acc+bias+resid
#define BM 128
#define BN 128
#define BKT 16
#define ASTR 20    /* A smem row stride (floats): conflict-free frag loads */
#define BSTR 136   /* B smem row stride (floats): conflict-free frag loads */

template<int EPI>
__global__ __launch_bounds__(256, 2) void gemm_tf32(
    const float* __restrict__ A, const float* __restrict__ B,
    float* __restrict__ C, int M, int N, int K,
    const float* __restrict__ bias, const float* __restrict__ resid)
{
    __shared__ float As[2][BM][ASTR];
    __shared__ float Bs[2][BKT][BSTR];
    int tid  = threadIdx.x;
    int lane = tid & 31;
    int wid  = tid >> 5;
    int g    = lane >> 2;     // 0..7
    int tg   = lane & 3;      // 0..3
    int wm   = wid & 1;       // warp row: 2 x 64
    int wn   = wid >> 1;      // warp col: 4 x 32
    int brow = blockIdx.y * BM;
    int bcol = blockIdx.x * BN;

    // global->smem load indices
    int ar  = tid >> 2;          // 0..63 (A row within tile, +64 second half)
    int ac  = (tid & 3) << 2;    // k offset 0,4,8,12
    int bkr = tid >> 5;          // 0..7  (B k-row, +8 second half)
    int bnc = (tid & 31) << 2;   // n offset 0..124

    const float* Ap0 = A + (size_t)(brow + ar) * K + ac;
    const float* Ap1 = A + (size_t)(brow + ar + 64) * K + ac;
    const float* Bp0 = B + (size_t)bkr * N + bcol + bnc;
    const float* Bp1 = B + (size_t)(bkr + 8) * N + bcol + bnc;

    uint32_t sA0[2], sA1[2], sB0[2], sB1[2];
    #pragma unroll
    for (int bf = 0; bf < 2; bf++) {
        sA0[bf] = (uint32_t)__cvta_generic_to_shared(&As[bf][ar][ac]);
        sA1[bf] = (uint32_t)__cvta_generic_to_shared(&As[bf][ar + 64][ac]);
        sB0[bf] = (uint32_t)__cvta_generic_to_shared(&Bs[bf][bkr][bnc]);
        sB1[bf] = (uint32_t)__cvta_generic_to_shared(&Bs[bf][bkr + 8][bnc]);
    }

    float acc[4][4][4];
    #pragma unroll
    for (int i = 0; i < 4; i++)
        #pragma unroll
        for (int j = 0; j < 4; j++)
            #pragma unroll
            for (int r = 0; r < 4; r++) acc[i][j][r] = 0.f;

    int niter = K / BKT;

    // prologue: load tile 0 into buf 0
    cpasync16(sA0[0], Ap0);
    cpasync16(sA1[0], Ap1);
    cpasync16(sB0[0], Bp0);
    cpasync16(sB1[0], Bp1);
    cpcommit();

    for (int it = 0; it < niter; it++) {
        int buf = it & 1;
        if (it + 1 < niter) {
            int k0 = (it + 1) * BKT;
            cpasync16(sA0[buf ^ 1], Ap0 + k0);
            cpasync16(sA1[buf ^ 1], Ap1 + k0);
            cpasync16(sB0[buf ^ 1], Bp0 + (size_t)k0 * N);
            cpasync16(sB1[buf ^ 1], Bp1 + (size_t)k0 * N);
            cpcommit();
            cpwait<1>();
        } else {
            cpwait<0>();
        }
        __syncthreads();

        #pragma unroll
        for (int ks = 0; ks < 2; ks++) {
            int kb = ks * 8;
            uint32_t a[4][4], b[4][2];
            #pragma unroll
            for (int mf = 0; mf < 4; mf++) {
                int m = wm * 64 + mf * 16 + g;
                a[mf][0] = __float_as_uint(As[buf][m    ][kb + tg    ]);
                a[mf][1] = __float_as_uint(As[buf][m + 8][kb + tg    ]);
                a[mf][2] = __float_as_uint(As[buf][m    ][kb + tg + 4]);
                a[mf][3] = __float_as_uint(As[buf][m + 8][kb + tg + 4]);
            }
            #pragma unroll
            for (int nf = 0; nf < 4; nf++) {
                int n = wn * 32 + nf * 8 + g;
                b[nf][0] = __float_as_uint(Bs[buf][kb + tg    ][n]);
                b[nf][1] = __float_as_uint(Bs[buf][kb + tg + 4][n]);
            }
            #pragma unroll
            for (int mf = 0; mf < 4; mf++)
                #pragma unroll
                for (int nf = 0; nf < 4; nf++)
                    mma_tf32(acc[mf][nf], a[mf][0], a[mf][1], a[mf][2], a[mf][3],
                             b[nf][0], b[nf][1]);
        }
        __syncthreads();
    }

    // epilogue
    #pragma unroll
    for (int mf = 0; mf < 4; mf++) {
        #pragma unroll
        for (int nf = 0; nf < 4; nf++) {
            int col = bcol + wn * 32 + nf * 8 + 2 * tg;
            #pragma unroll
            for (int rr = 0; rr < 2; rr++) {
                int row = brow + wm * 64 + mf * 16 + g + rr * 8;
                size_t off = (size_t)row * N + col;
                float v0 = acc[mf][nf][rr * 2 + 0];
                float v1 = acc[mf][nf][rr * 2 + 1];
                if (EPI == 2 || EPI == 3) {
                    v0 += bias[col];
                    v1 += bias[col + 1];
                }
                if (EPI == 1 || EPI == 3) {
                    float2 rv = *(const float2*)(resid + off);
                    v0 += rv.x;
                    v1 += rv.y;
                }
                if (EPI == 2) {
                    v0 = tf32r(gelu_exact(v0));
                    v1 = tf32r(gelu_exact(v1));
                }
                float2 o;
                o.x = v0; o.y = v1;
                *(float2*)(C + off) = o;
            }
        }
    }
}

// ---------------- Causal flash attention v2 (fp32, split-D x2, online softmax) --------
// grid (S/128, NH, B); 256 threads; lane pair (2t, 2t+1) owns query blockIdx.x*128 + t,
// each lane handles 32 of 64 head dims. Causal branch is warp-uniform.
__global__ __launch_bounds__(256) void attn_kernel(
    const float* __restrict__ qkv, float* __restrict__ ctx)
{
    const int C3 = 3 * D_;
    int b = blockIdx.z, h = blockIdx.y;
    int ql   = threadIdx.x >> 1;      // 0..127
    int half = threadIdx.x & 1;       // which 32-dim half
    int q = blockIdx.x * 128 + ql;
    const float* base = qkv + (size_t)b * S_ * C3 + h * DH_;

    __shared__ float Ks[16][DH_];
    __shared__ float Vs[16][DH_];

    float qreg[32];
    {
        const float4* qp = (const float4*)(base + (size_t)q * C3 + half * 32);
        #pragma unroll
        for (int i = 0; i < 8; i++) {
            float4 v = qp[i];
            qreg[4*i+0] = v.x; qreg[4*i+1] = v.y;
            qreg[4*i+2] = v.z; qreg[4*i+3] = v.w;
        }
    }
    float acc[32];
    #pragma unroll
    for (int i = 0; i < 32; i++) acc[i] = 0.f;
    float m = -1e30f, l = 0.f;

    int r  = threadIdx.x >> 4;   // 0..15 (K/V coop-load row)
    int c4 = threadIdx.x & 15;   // float4 col
    int qmax = blockIdx.x * 128 + 127;

    for (int kt = 0; kt <= qmax; kt += 16) {
        ((float4*)Ks[r])[c4] = ((const float4*)(base +     D_ + (size_t)(kt + r) * C3))[c4];
        ((float4*)Vs[r])[c4] = ((const float4*)(base + 2 * D_ + (size_t)(kt + r) * C3))[c4];
        __syncthreads();

        if (q >= kt) {   // warp-uniform (16 aligned queries vs 16 aligned keys)
            float s[16];
            #pragma unroll
            for (int kk = 0; kk < 16; kk++) {
                const float4* kr = (const float4*)(&Ks[kk][half * 32]);
                float sa0 = 0.f, sa1 = 0.f;
                #pragma unroll
                for (int d4 = 0; d4 < 8; d4 += 2) {
                    float4 k0 = kr[d4], k1 = kr[d4 + 1];
                    sa0 += qreg[4*d4+0]*k0.x + qreg[4*d4+1]*k0.y
                         + qreg[4*d4+2]*k0.z + qreg[4*d4+3]*k0.w;
                    sa1 += qreg[4*d4+4]*k1.x + qreg[4*d4+5]*k1.y
                         + qreg[4*d4+6]*k1.z + qreg[4*d4+7]*k1.w;
                }
                s[kk] = sa0 + sa1;
            }
            #pragma unroll
            for (int kk = 0; kk < 16; kk++)
                s[kk] += __shfl_xor_sync(0xFFFFFFFFu, s[kk], 1);
            #pragma unroll
            for (int kk = 0; kk < 16; kk++)
                s[kk] = (kt + kk <= q) ? s[kk] * 0.125f : -1e30f;

            float tmax = -1e30f;
            #pragma unroll
            for (int kk = 0; kk < 16; kk++) tmax = fmaxf(tmax, s[kk]);
            float mn = fmaxf(m, tmax);
            float rescale = __expf(m - mn);
            l *= rescale;
            #pragma unroll
            for (int d = 0; d < 32; d++) acc[d] *= rescale;
            m = mn;
            #pragma unroll
            for (int kk = 0; kk < 16; kk++) {
                float p = __expf(s[kk] - mn);
                l += p;
                const float4* vr = (const float4*)(&Vs[kk][half * 32]);
                #pragma unroll
                for (int d4 = 0; d4 < 8; d4++) {
                    float4 v = vr[d4];
                    acc[4*d4+0] += p * v.x;
                    acc[4*d4+1] += p * v.y;
                    acc[4*d4+2] += p * v.z;
                    acc[4*d4+3] += p * v.w;
                }
            }
        }
        __syncthreads();
    }

    float inv = 1.0f / l;
    float4* op = (float4*)(ctx + ((size_t)b * S_ + q) * D_ + h * DH_ + half * 32);
    #pragma unroll
    for (int d4 = 0; d4 < 8; d4++) {
        float4 o;
        o.x = tf32r(acc[4*d4+0] * inv);
        o.y = tf32r(acc[4*d4+1] * inv);
        o.z = tf32r(acc[4*d4+2] * inv);
        o.w = tf32r(acc[4*d4+3] * inv);
        op[d4] = o;
    }
}

// ---------------- launch ----------------
extern "C" void kernel_launch(void* const* d_in, const int* in_sizes, int n_in,
                              void* d_out, int out_size)
{
    const float* x    = (const float*)d_in[0];
    const float* WQ   = (const float*)d_in[1];
    const float* WK   = (const float*)d_in[2];
    const float* WV   = (const float*)d_in[3];
    const float* WO   = (const float*)d_in[4];   // [NH,DH,D] flat == [1024,1024] row-major
    const float* W1   = (const float*)d_in[5];   // [1024,4096]
    const float* b1   = (const float*)d_in[6];
    const float* W2   = (const float*)d_in[7];   // [4096,1024]
    const float* b2   = (const float*)d_in[8];
    const float* ln1w = (const float*)d_in[9];
    const float* ln1b = (const float*)d_in[10];
    const float* ln2w = (const float*)d_in[11];
    const float* ln2b = (const float*)d_in[12];
    float* out = (float*)d_out;

    float *h1, *qkv, *ctx, *x1, *h2, *mid, *wqkv, *wo, *w1, *w2;
    cudaGetSymbolAddress((void**)&h1,   g_h1);
    cudaGetSymbolAddress((void**)&qkv,  g_qkv);
    cudaGetSymbolAddress((void**)&ctx,  g_ctx);
    cudaGetSymbolAddress((void**)&x1,   g_x1);
    cudaGetSymbolAddress((void**)&h2,   g_h2);
    cudaGetSymbolAddress((void**)&mid,  g_mid);
    cudaGetSymbolAddress((void**)&wqkv, g_wqkv);
    cudaGetSymbolAddress((void**)&wo,   g_wo);
    cudaGetSymbolAddress((void**)&w1,   g_w1);
    cudaGetSymbolAddress((void**)&w2,   g_w2);

    // weight prep (tf32 rounding happens once here, not in GEMM mainloops)
    pack_qkv_kernel<<<(D_ * 3 * D_) / 256, 256>>>(WQ, WK, WV, wqkv);
    cvt_kernel<<<(D_ * D_) / 256, 256>>>(WO, wo, D_ * D_);
    cvt_kernel<<<(D_ * DM_) / 256, 256>>>(W1, w1, D_ * DM_);
    cvt_kernel<<<(DM_ * D_) / 256, 256>>>(W2, w2, DM_ * D_);

    // LN1 (tf32-rounded output: feeds QKV GEMM)
    ln_kernel<true><<<M_, 256>>>(x, ln1w, ln1b, h1);

    // QKV projection: [4096,1024] @ [1024,3072] (full-precision fp32 output for attention)
    {
        dim3 g(3 * D_ / BN, M_ / BM);
        gemm_tf32<0><<<g, 256>>>(h1, wqkv, qkv, M_, 3 * D_, D_, nullptr, nullptr);
    }
    // causal attention (tf32-rounded ctx: feeds WO GEMM)
    {
        dim3 g(S_ / 128, NH_, B_);
        attn_kernel<<<g, 256>>>(qkv, ctx);
    }
    // output projection + residual: x1 = x + ctx @ WO
    {
        dim3 g(D_ / BN, M_ / BM);
        gemm_tf32<1><<<g, 256>>>(ctx, wo, x1, M_, D_, D_, nullptr, x);
    }
    // LN2 (tf32-rounded output: feeds W1 GEMM)
    ln_kernel<true><<<M_, 256>>>(x1, ln2w, ln2b, h2);
    // MLP up + GELU: mid = tf32(gelu(h2 @ W1 + b1))
    {
        dim3 g(DM_ / BN, M_ / BM);
        gemm_tf32<2><<<g, 256>>>(h2, w1, mid, M_, DM_, D_, b1, nullptr);
    }
    // MLP down + bias + residual: out = x1 + mid @ W2 + b2
    {
        dim3 g(D_ / BN, M_ / BM);
        gemm_tf32<3><<<g, 256>>>(mid, w2, out, M_, D_, DM_, b2, x1);
    }
}

// round 9
// speedup vs baseline: 1.7628x; 1.0649x over previous
#include <cuda_runtime.h>
#include <math.h>
#include <stdint.h>

#define D_    1024
#define NH_   16
#define DH_   64
#define DM_   4096
#define B_    2
#define S_    2048
#define M_    (B_*S_)   /* 4096 rows */

// ---------------- scratch (static device allocations; no cudaMalloc) ----------------
__device__ float g_h1  [(size_t)M_*D_];     // LN1 output (tf32-rounded)
__device__ float g_qkv [(size_t)M_*3*D_];   // fused QKV (full fp32)
__device__ float g_ctx [(size_t)M_*D_];     // attention context (tf32-rounded)
__device__ float g_x1  [(size_t)M_*D_];     // x + attn_out
__device__ float g_h2  [(size_t)M_*D_];     // LN2 output (tf32-rounded)
__device__ float g_mid [(size_t)M_*DM_];    // MLP hidden post-GELU (tf32-rounded)
__device__ float g_wqkv[(size_t)D_*3*D_];   // repacked QKV weight [D][3*NH*DH] (tf32)
__device__ float g_wo  [(size_t)D_*D_];     // tf32-rounded WO [D][D]
__device__ float g_w1  [(size_t)D_*DM_];    // tf32-rounded W1 [D][DM]
__device__ float g_w2  [(size_t)DM_*D_];    // tf32-rounded W2 [DM][D]

// ---------------- helpers ----------------
__device__ __forceinline__ float gelu_exact(float x) {
    return 0.5f * x * (1.0f + erff(x * 0.70710678118654752440f));
}
__device__ __forceinline__ float tf32r(float x) {
    float y;
    asm("cvt.rna.tf32.f32 %0, %1;" : "=f"(y) : "f"(x));
    return y;
}
__device__ __forceinline__ void cpasync16(uint32_t dst, const void* src) {
    asm volatile("cp.async.cg.shared.global [%0], [%1], 16;" :: "r"(dst), "l"(src));
}
__device__ __forceinline__ void cpcommit() {
    asm volatile("cp.async.commit_group;");
}
template<int N>
__device__ __forceinline__ void cpwait() {
    asm volatile("cp.async.wait_group %0;" :: "n"(N));
}
__device__ __forceinline__ void mma_tf32(float c[4], uint32_t a0, uint32_t a1,
                                         uint32_t a2, uint32_t a3,
                                         uint32_t b0, uint32_t b1) {
    asm volatile(
        "mma.sync.aligned.m16n8k8.row.col.f32.tf32.tf32.f32 "
        "{%0,%1,%2,%3}, {%4,%5,%6,%7}, {%8,%9}, {%0,%1,%2,%3};"
        : "+f"(c[0]), "+f"(c[1]), "+f"(c[2]), "+f"(c[3])
        : "r"(a0), "r"(a1), "r"(a2), "r"(a3), "r"(b0), "r"(b1));
}

// ---------------- elementwise tf32 convert ----------------
__global__ __launch_bounds__(256) void cvt_kernel(const float* __restrict__ in,
                                                  float* __restrict__ out, int n) {
    int i = blockIdx.x * 256 + threadIdx.x;
    if (i < n) out[i] = tf32r(in[i]);
}

// ---------------- QKV weight repack: [NH,D,DH] x3 -> [D, 3*NH*DH], tf32-rounded --------
__global__ __launch_bounds__(256) void pack_qkv_kernel(
    const float* __restrict__ WQ, const float* __restrict__ WK,
    const float* __restrict__ WV, float* __restrict__ Wp)
{
    int idx = blockIdx.x * 256 + threadIdx.x;
    int col = idx % (3 * D_);
    int d   = idx / (3 * D_);
    int seg = col >> 10;
    int hc  = col & 1023;
    int h   = hc >> 6;
    int e   = hc & 63;
    const float* W = (seg == 0) ? WQ : (seg == 1) ? WK : WV;
    Wp[idx] = tf32r(W[((size_t)h * D_ + d) * DH_ + e]);
}

// ---------------- LayerNorm (tf32-rounded output) ----------------
__global__ __launch_bounds__(256) void ln_kernel(
    const float* __restrict__ x, const float* __restrict__ w,
    const float* __restrict__ b, float* __restrict__ out)
{
    int row = blockIdx.x;
    int t   = threadIdx.x;
    const float4* xr = (const float4*)(x + (size_t)row * D_);
    float4 v = xr[t];
    float s  = v.x + v.y + v.z + v.w;
    float sq = v.x*v.x + v.y*v.y + v.z*v.z + v.w*v.w;
    #pragma unroll
    for (int o = 16; o; o >>= 1) {
        s  += __shfl_xor_sync(0xFFFFFFFFu, s,  o);
        sq += __shfl_xor_sync(0xFFFFFFFFu, sq, o);
    }
    __shared__ float ss[8], sqs[8];
    int wid = t >> 5, lid = t & 31;
    if (lid == 0) { ss[wid] = s; sqs[wid] = sq; }
    __syncthreads();
    s = 0.f; sq = 0.f;
    #pragma unroll
    for (int i = 0; i < 8; i++) { s += ss[i]; sq += sqs[i]; }
    float mu  = s  * (1.0f / D_);
    float var = sq * (1.0f / D_) - mu * mu;
    float rs  = rsqrtf(var + 1e-5f);
    float4 wv = ((const float4*)w)[t];
    float4 bv = ((const float4*)b)[t];
    float4 o;
    o.x = tf32r((v.x - mu) * rs * wv.x + bv.x);
    o.y = tf32r((v.y - mu) * rs * wv.y + bv.y);
    o.z = tf32r((v.z - mu) * rs * wv.z + bv.z);
    o.w = tf32r((v.w - mu) * rs * wv.w + bv.w);
    ((float4*)(out + (size_t)row * D_))[t] = o;
}

// ---------------- TF32 tensor-core GEMM v2: C[M,N] = A[M,K] @ B[K,N] ----------------
// 128x128 block tile, 4 warps (2x2) of 64x64, KT=32, dynamic smem, 2-stage cp.async.
// LDS/MMA ratio 1.0 (vs 1.5 in v1): A and B fragments both reused 8x/4x in registers.
// EPI: 0 = plain, 1 = +resid, 2 = tf32(gelu(acc+bias)), 3 = acc+bias+resid
#define BM 128
#define BN 128
#define BKT 32
#define ASTR 36     /* A smem row stride (floats), rows=BM   : banks 4g+tg perm */
#define BSTR 136    /* B smem row stride (floats), rows=BKT  : banks 8tg+g perm */
#define A_STAGE (BM * ASTR)            /* 4608 floats = 18432 B */
#define B_STAGE (BKT * BSTR)           /* 4352 floats = 17408 B */
#define GSMEM   ((2 * A_STAGE + 2 * B_STAGE) * 4)   /* 71680 B */

template<int EPI>
__global__ __launch_bounds__(128, 2) void gemm_tf32(
    const float* __restrict__ A, const float* __restrict__ B,
    float* __restrict__ C, int M, int N, int K,
    const float* __restrict__ bias, const float* __restrict__ resid)
{
    extern __shared__ float sm[];
    float* As = sm;                       // [2][BM][ASTR]
    float* Bs = sm + 2 * A_STAGE;         // [2][BKT][BSTR]
    uint32_t sA = (uint32_t)__cvta_generic_to_shared(As);
    uint32_t sB = (uint32_t)__cvta_generic_to_shared(Bs);

    int tid  = threadIdx.x;
    int lane = tid & 31;
    int wid  = tid >> 5;
    int g    = lane >> 2;     // 0..7
    int tg   = lane & 3;      // 0..3
    int wm   = wid & 1;       // warp row (2 x 64)
    int wn   = wid >> 1;      // warp col (2 x 64)
    int brow = blockIdx.y * BM;
    int bcol = blockIdx.x * BN;

    // global->smem load indices (coalesced 16B chunks)
    int arow0 = tid >> 3;            // 0..15, step 16 -> 128 rows over 8 iters
    int akc   = (tid & 7) * 4;       // k-float offset 0..28
    int bkr0  = tid >> 5;            // 0..3, step 4 -> 32 k-rows over 8 iters
    int bnc   = (tid & 31) * 4;      // n-float offset 0..124

    float acc[4][8][4];
    #pragma unroll
    for (int i = 0; i < 4; i++)
        #pragma unroll
        for (int j = 0; j < 8; j++)
            #pragma unroll
            for (int r = 0; r < 4; r++) acc[i][j][r] = 0.f;

    int nt = K / BKT;

    // prologue: stage 0 -> buf 0
    {
        #pragma unroll
        for (int i = 0; i < 8; i++) {
            int ar = arow0 + i * 16;
            cpasync16(sA + ((size_t)0 + (size_t)ar * ASTR + akc) * 4,
                      A + (size_t)(brow + ar) * K + akc);
            int br = bkr0 + i * 4;
            cpasync16(sB + ((size_t)0 + (size_t)br * BSTR + bnc) * 4,
                      B + (size_t)br * N + bcol + bnc);
        }
        cpcommit();
    }

    for (int t = 0; t < nt; t++) {
        int buf = t & 1;
        if (t + 1 < nt) {
            int k0 = (t + 1) * BKT;
            int nb = buf ^ 1;
            #pragma unroll
            for (int i = 0; i < 8; i++) {
                int ar = arow0 + i * 16;
                cpasync16(sA + ((size_t)nb * A_STAGE + (size_t)ar * ASTR + akc) * 4,
                          A + (size_t)(brow + ar) * K + k0 + akc);
                int br = bkr0 + i * 4;
                cpasync16(sB + ((size_t)nb * B_STAGE + (size_t)br * BSTR + bnc) * 4,
                          B + (size_t)(k0 + br) * N + bcol + bnc);
            }
            cpcommit();
            cpwait<1>();
        } else {
            cpwait<0>();
        }
        __syncthreads();

        const float* Ab = As + (size_t)buf * A_STAGE;
        const float* Bb = Bs + (size_t)buf * B_STAGE;
        #pragma unroll
        for (int ks = 0; ks < 4; ks++) {
            int kb = ks * 8;
            uint32_t a[4][4], b[8][2];
            #pragma unroll
            for (int mf = 0; mf < 4; mf++) {
                int m = wm * 64 + mf * 16 + g;
                a[mf][0] = __float_as_uint(Ab[(size_t)(m    ) * ASTR + kb + tg    ]);
                a[mf][1] = __float_as_uint(Ab[(size_t)(m + 8) * ASTR + kb + tg    ]);
                a[mf][2] = __float_as_uint(Ab[(size_t)(m    ) * ASTR + kb + tg + 4]);
                a[mf][3] = __float_as_uint(Ab[(size_t)(m + 8) * ASTR + kb + tg + 4]);
            }
            #pragma unroll
            for (int nf = 0; nf < 8; nf++) {
                int n = wn * 64 + nf * 8 + g;
                b[nf][0] = __float_as_uint(Bb[(size_t)(kb + tg    ) * BSTR + n]);
                b[nf][1] = __float_as_uint(Bb[(size_t)(kb + tg + 4) * BSTR + n]);
            }
            #pragma unroll
            for (int mf = 0; mf < 4; mf++)
                #pragma unroll
                for (int nf = 0; nf < 8; nf++)
                    mma_tf32(acc[mf][nf], a[mf][0], a[mf][1], a[mf][2], a[mf][3],
                             b[nf][0], b[nf][1]);
        }
        __syncthreads();
    }

    // epilogue
    #pragma unroll
    for (int mf = 0; mf < 4; mf++) {
        #pragma unroll
        for (int nf = 0; nf < 8; nf++) {
            int col = bcol + wn * 64 + nf * 8 + 2 * tg;
            #pragma unroll
            for (int rr = 0; rr < 2; rr++) {
                int row = brow + wm * 64 + mf * 16 + g + rr * 8;
                size_t off = (size_t)row * N + col;
                float v0 = acc[mf][nf][rr * 2 + 0];
                float v1 = acc[mf][nf][rr * 2 + 1];
                if (EPI == 2 || EPI == 3) {
                    v0 += bias[col];
                    v1 += bias[col + 1];
                }
                if (EPI == 1 || EPI == 3) {
                    float2 rv = *(const float2*)(resid + off);
                    v0 += rv.x;
                    v1 += rv.y;
                }
                if (EPI == 2) {
                    v0 = tf32r(gelu_exact(v0));
                    v1 = tf32r(gelu_exact(v1));
                }
                float2 o;
                o.x = v0; o.y = v1;
                *(float2*)(C + off) = o;
            }
        }
    }
}

// ---------------- Causal flash attention (fp32, split-D x2, online softmax) --------
// grid (S/128, NH, B); 256 threads; lane pair (2t, 2t+1) owns query blockIdx.x*128 + t,
// each lane handles 32 of 64 head dims. Causal branch is warp-uniform.
__global__ __launch_bounds__(256) void attn_kernel(
    const float* __restrict__ qkv, float* __restrict__ ctx)
{
    const int C3 = 3 * D_;
    int b = blockIdx.z, h = blockIdx.y;
    int ql   = threadIdx.x >> 1;
    int half = threadIdx.x & 1;
    int q = blockIdx.x * 128 + ql;
    const float* base = qkv + (size_t)b * S_ * C3 + h * DH_;

    __shared__ float Ks[16][DH_];
    __shared__ float Vs[16][DH_];

    float qreg[32];
    {
        const float4* qp = (const float4*)(base + (size_t)q * C3 + half * 32);
        #pragma unroll
        for (int i = 0; i < 8; i++) {
            float4 v = qp[i];
            qreg[4*i+0] = v.x; qreg[4*i+1] = v.y;
            qreg[4*i+2] = v.z; qreg[4*i+3] = v.w;
        }
    }
    float acc[32];
    #pragma unroll
    for (int i = 0; i < 32; i++) acc[i] = 0.f;
    float m = -1e30f, l = 0.f;

    int r  = threadIdx.x >> 4;
    int c4 = threadIdx.x & 15;
    int qmax = blockIdx.x * 128 + 127;

    for (int kt = 0; kt <= qmax; kt += 16) {
        ((float4*)Ks[r])[c4] = ((const float4*)(base +     D_ + (size_t)(kt + r) * C3))[c4];
        ((float4*)Vs[r])[c4] = ((const float4*)(base + 2 * D_ + (size_t)(kt + r) * C3))[c4];
        __syncthreads();

        if (q >= kt) {
            float s[16];
            #pragma unroll
            for (int kk = 0; kk < 16; kk++) {
                const float4* kr = (const float4*)(&Ks[kk][half * 32]);
                float sa0 = 0.f, sa1 = 0.f;
                #pragma unroll
                for (int d4 = 0; d4 < 8; d4 += 2) {
                    float4 k0 = kr[d4], k1 = kr[d4 + 1];
                    sa0 += qreg[4*d4+0]*k0.x + qreg[4*d4+1]*k0.y
                         + qreg[4*d4+2]*k0.z + qreg[4*d4+3]*k0.w;
                    sa1 += qreg[4*d4+4]*k1.x + qreg[4*d4+5]*k1.y
                         + qreg[4*d4+6]*k1.z + qreg[4*d4+7]*k1.w;
                }
                s[kk] = sa0 + sa1;
            }
            #pragma unroll
            for (int kk = 0; kk < 16; kk++)
                s[kk] += __shfl_xor_sync(0xFFFFFFFFu, s[kk], 1);
            #pragma unroll
            for (int kk = 0; kk < 16; kk++)
                s[kk] = (kt + kk <= q) ? s[kk] * 0.125f : -1e30f;

            float tmax = -1e30f;
            #pragma unroll
            for (int kk = 0; kk < 16; kk++) tmax = fmaxf(tmax, s[kk]);
            float mn = fmaxf(m, tmax);
            float rescale = __expf(m - mn);
            l *= rescale;
            #pragma unroll
            for (int d = 0; d < 32; d++) acc[d] *= rescale;
            m = mn;
            #pragma unroll
            for (int kk = 0; kk < 16; kk++) {
                float p = __expf(s[kk] - mn);
                l += p;
                const float4* vr = (const float4*)(&Vs[kk][half * 32]);
                #pragma unroll
                for (int d4 = 0; d4 < 8; d4++) {
                    float4 v = vr[d4];
                    acc[4*d4+0] += p * v.x;
                    acc[4*d4+1] += p * v.y;
                    acc[4*d4+2] += p * v.z;
                    acc[4*d4+3] += p * v.w;
                }
            }
        }
        __syncthreads();
    }

    float inv = 1.0f / l;
    float4* op = (float4*)(ctx + ((size_t)b * S_ + q) * D_ + h * DH_ + half * 32);
    #pragma unroll
    for (int d4 = 0; d4 < 8; d4++) {
        float4 o;
        o.x = tf32r(acc[4*d4+0] * inv);
        o.y = tf32r(acc[4*d4+1] * inv);
        o.z = tf32r(acc[4*d4+2] * inv);
        o.w = tf32r(acc[4*d4+3] * inv);
        op[d4] = o;
    }
}

// ---------------- launch ----------------
extern "C" void kernel_launch(void* const* d_in, const int* in_sizes, int n_in,
                              void* d_out, int out_size)
{
    const float* x    = (const float*)d_in[0];
    const float* WQ   = (const float*)d_in[1];
    const float* WK   = (const float*)d_in[2];
    const float* WV   = (const float*)d_in[3];
    const float* WO   = (const float*)d_in[4];   // [NH*DH, D] row-major = [1024,1024]
    const float* W1   = (const float*)d_in[5];   // [1024,4096]
    const float* b1   = (const float*)d_in[6];
    const float* W2   = (const float*)d_in[7];   // [4096,1024]
    const float* b2   = (const float*)d_in[8];
    const float* ln1w = (const float*)d_in[9];
    const float* ln1b = (const float*)d_in[10];
    const float* ln2w = (const float*)d_in[11];
    const float* ln2b = (const float*)d_in[12];
    float* out = (float*)d_out;

    float *h1, *qkv, *ctx, *x1, *h2, *mid, *wqkv, *wo, *w1, *w2;
    cudaGetSymbolAddress((void**)&h1,   g_h1);
    cudaGetSymbolAddress((void**)&qkv,  g_qkv);
    cudaGetSymbolAddress((void**)&ctx,  g_ctx);
    cudaGetSymbolAddress((void**)&x1,   g_x1);
    cudaGetSymbolAddress((void**)&h2,   g_h2);
    cudaGetSymbolAddress((void**)&mid,  g_mid);
    cudaGetSymbolAddress((void**)&wqkv, g_wqkv);
    cudaGetSymbolAddress((void**)&wo,   g_wo);
    cudaGetSymbolAddress((void**)&w1,   g_w1);
    cudaGetSymbolAddress((void**)&w2,   g_w2);

    // dynamic smem opt-in (idempotent)
    cudaFuncSetAttribute(gemm_tf32<0>, cudaFuncAttributeMaxDynamicSharedMemorySize, GSMEM);
    cudaFuncSetAttribute(gemm_tf32<1>, cudaFuncAttributeMaxDynamicSharedMemorySize, GSMEM);
    cudaFuncSetAttribute(gemm_tf32<2>, cudaFuncAttributeMaxDynamicSharedMemorySize, GSMEM);
    cudaFuncSetAttribute(gemm_tf32<3>, cudaFuncAttributeMaxDynamicSharedMemorySize, GSMEM);

    // weight prep (tf32 rounding once; layouts stay [K][N])
    pack_qkv_kernel<<<(D_ * 3 * D_) / 256, 256>>>(WQ, WK, WV, wqkv);
    cvt_kernel<<<(D_ * D_) / 256, 256>>>(WO, wo, D_ * D_);
    cvt_kernel<<<(D_ * DM_) / 256, 256>>>(W1, w1, D_ * DM_);
    cvt_kernel<<<(DM_ * D_) / 256, 256>>>(W2, w2, DM_ * D_);

    // LN1
    ln_kernel<<<M_, 256>>>(x, ln1w, ln1b, h1);

    // QKV projection: [4096,1024] @ [1024,3072]
    gemm_tf32<0><<<dim3(3 * D_ / BN, M_ / BM), 128, GSMEM>>>(
        h1, wqkv, qkv, M_, 3 * D_, D_, nullptr, nullptr);
    // causal attention
    {
        dim3 g(S_ / 128, NH_, B_);
        attn_kernel<<<g, 256>>>(qkv, ctx);
    }
    // output projection + residual: x1 = x + ctx @ WO
    gemm_tf32<1><<<dim3(D_ / BN, M_ / BM), 128, GSMEM>>>(
        ctx, wo, x1, M_, D_, D_, nullptr, x);
    // LN2
    ln_kernel<<<M_, 256>>>(x1, ln2w, ln2b, h2);
    // MLP up + GELU
    gemm_tf32<2><<<dim3(DM_ / BN, M_ / BM), 128, GSMEM>>>(
        h2, w1, mid, M_, DM_, D_, b1, nullptr);
    // MLP down + bias + residual
    gemm_tf32<3><<<dim3(D_ / BN, M_ / BM), 128, GSMEM>>>(
        mid, w2, out, M_, D_, DM_, b2, x1);
}